// round 1
// baseline (speedup 1.0000x reference)
#include <cuda_runtime.h>
#include <math.h>

#define BB 8
#define CC 32
#define SS 256
#define HP 288
#define KY 12
#define MM 24
#define NLAY 4
#define PLANE (HP*HP)

// ---------------- device scratch (static, no allocation) ----------------
__device__ float  g_h0[BB*CC*PLANE];
__device__ float  g_h1[BB*CC*PLANE];
__device__ float2 g_G [BB*CC*HP*KY];
__device__ float2 g_F [BB*CC*MM*KY];
__device__ float2 g_O [BB*CC*MM*KY];
__device__ float2 g_T [BB*CC*HP*KY];
__device__ float  g_Wtr[NLAY*MM*KY*CC*CC];
__device__ float  g_Wti[NLAY*MM*KY*CC*CC];
__device__ float2 g_Ey [KY*HP];   // [ky][y]  e^{-2pi i ky y / 288}
__device__ float2 g_Ex [MM*HP];   // [m][x]   e^{-2pi i kx(m) x / 288}
__device__ float2 g_Exi[MM*HP];   // [m][x]   e^{+2pi i kx(m) x / 288}
__device__ float  g_ICy[KY*HP];   // alpha*cos(+ang)/(288^2)
__device__ float  g_ISy[KY*HP];   // alpha*sin(+ang)/(288^2)
__device__ float  g_tmp[BB*2*SS*SS];

__device__ __forceinline__ float gelu_exact(float x) {
    return 0.5f * x * (1.0f + erff(x * 0.70710678118654752440f));
}

// ---------------- basis tables ----------------
__global__ void k_basis() {
    int idx = blockIdx.x * blockDim.x + threadIdx.x;
    if (idx < KY*HP) {
        int ky = idx / HP, y = idx % HP;
        int r = (ky * y) % HP;
        float a = 6.28318530717958647692f * (float)r / (float)HP;
        float c = cosf(a), s = sinf(a);
        g_Ey[idx] = make_float2(c, -s);
        float al = (ky == 0) ? 1.0f : 2.0f;
        float inv = 1.0f / ((float)HP * (float)HP);
        g_ICy[idx] = al * inv * c;
        g_ISy[idx] = al * inv * s;
    }
    if (idx < MM*HP) {
        int m = idx / HP, xx = idx % HP;
        int kx = (m < KY) ? m : (264 + m);   // m=12..23 -> 276..287
        int r = (kx * xx) % HP;
        float a = 6.28318530717958647692f * (float)r / (float)HP;
        float c = cosf(a), s = sinf(a);
        g_Ex[idx]  = make_float2(c, -s);
        g_Exi[idx] = make_float2(c,  s);
    }
}

// ---------------- weight transpose: [l][i][o][kx][ky] -> [l][m][ky][i][o] ----------------
__global__ void k_transw(const float* __restrict__ w1r, const float* __restrict__ w1i,
                         const float* __restrict__ w2r, const float* __restrict__ w2i) {
    int idx = blockIdx.x * blockDim.x + threadIdx.x;
    if (idx >= NLAY*MM*KY*CC*CC) return;
    int o  = idx & 31;
    int i  = (idx >> 5) & 31;
    int ky = (idx >> 10) % KY;
    int rest = idx / (1024 * KY);
    int m = rest % MM;
    int l = rest / MM;
    const float *sr, *si;
    int src;
    if (m < KY) {
        src = (((l*CC + i)*CC + o)*12 + m)*12 + ky;
        sr = w1r; si = w1i;
    } else {
        src = (((l*CC + i)*CC + o)*12 + (m - 12))*12 + ky;
        sr = w2r; si = w2i;
    }
    g_Wtr[idx] = sr[src];
    g_Wti[idx] = si[src];
}

// ---------------- stage 0: gather + grid + fc0 (3->32), zero pad ----------------
__global__ void k_embed(const float* __restrict__ xin, const int* __restrict__ d2v,
                        const float* __restrict__ fw, const float* __restrict__ fb,
                        float* __restrict__ hout) {
    int idx = blockIdx.x * blockDim.x + threadIdx.x;
    if (idx >= BB*PLANE) return;
    int b = idx / PLANE;
    int rem = idx % PLANE;
    int i = rem / HP, j = rem % HP;
    float* hp = hout + (size_t)b * CC * PLANE + rem;
    if (i < SS && j < SS) {
        float v  = xin[b*SS*SS + d2v[i*SS + j]];
        float gi = (float)i * (1.0f/255.0f);
        float gj = (float)j * (1.0f/255.0f);
        #pragma unroll
        for (int c = 0; c < CC; c++)
            hp[(size_t)c*PLANE] = fw[c*3]*v + fw[c*3+1]*gi + fw[c*3+2]*gj + fb[c];
    } else {
        #pragma unroll
        for (int c = 0; c < CC; c++) hp[(size_t)c*PLANE] = 0.0f;
    }
}

// ---------------- A: truncated y-DFT ----------------
// grid (B*C, 18), block 128 = 16 rows x 8 strips
__global__ void __launch_bounds__(128) k_ydft(const float* __restrict__ h) {
    __shared__ float2 sEy[KY*HP];
    int t = threadIdx.x;
    for (int i = t; i < KY*HP; i += 128) sEy[i] = g_Ey[i];
    __syncthreads();
    int bc = blockIdx.x;
    int r = t >> 3, s = t & 7;
    int x = blockIdx.y * 16 + r;
    const float* row = h + (size_t)bc * PLANE + (size_t)x * HP;
    float ar[KY], ai[KY];
    #pragma unroll
    for (int q = 0; q < KY; q++) { ar[q] = 0.0f; ai[q] = 0.0f; }
    for (int k = 0; k < 36; k++) {
        int y = s + 8*k;
        float hv = row[y];
        #pragma unroll
        for (int q = 0; q < KY; q++) {
            float2 e = sEy[q*HP + y];
            ar[q] += hv * e.x;
            ai[q] += hv * e.y;
        }
    }
    #pragma unroll
    for (int q = 0; q < KY; q++) {
        #pragma unroll
        for (int d = 1; d < 8; d <<= 1) {
            ar[q] += __shfl_xor_sync(0xffffffffu, ar[q], d);
            ai[q] += __shfl_xor_sync(0xffffffffu, ai[q], d);
        }
    }
    if (s == 0) {
        float2* out = g_G + ((size_t)bc * HP + x) * KY;
        #pragma unroll
        for (int q = 0; q < KY; q++) out[q] = make_float2(ar[q], ai[q]);
    }
}

// ---------------- B: x-DFT onto 24 modes ----------------
// grid B*C, block 288 (thread = (m,ky))
__global__ void __launch_bounds__(288) k_xdft() {
    __shared__ float2 sG[HP*KY];
    int bc = blockIdx.x, t = threadIdx.x;
    const float2* Gp = g_G + (size_t)bc * HP * KY;
    for (int i = t; i < HP*KY; i += 288) sG[i] = Gp[i];
    __syncthreads();
    int m = t / KY, ky = t % KY;
    float accx = 0.0f, accy = 0.0f;
    const float2* ex = g_Ex + m * HP;
    for (int x = 0; x < HP; x++) {
        float2 g = sG[x*KY + ky];
        float2 e = ex[x];
        accx += g.x*e.x - g.y*e.y;
        accy += g.x*e.y + g.y*e.x;
    }
    g_F[((size_t)bc * MM + m) * KY + ky] = make_float2(accx, accy);
}

// ---------------- C: complex channel mix ----------------
// grid B*MM*KY, block 32 (thread = o)
__global__ void k_mix(int l) {
    int blk = blockIdx.x;
    int b  = blk / (MM*KY);
    int mk = blk % (MM*KY);
    int o = threadIdx.x;
    __shared__ float2 sF[CC];
    sF[o] = g_F[(size_t)(b*CC + o) * (MM*KY) + mk];
    __syncthreads();
    const float* wr = g_Wtr + ((size_t)l * MM * KY + mk) * CC * CC;
    const float* wi = g_Wti + ((size_t)l * MM * KY + mk) * CC * CC;
    float accr = 0.0f, acci = 0.0f;
    #pragma unroll 4
    for (int i = 0; i < CC; i++) {
        float2 f = sF[i];
        float a = wr[i*CC + o], bw = wi[i*CC + o];
        accr += f.x*a  - f.y*bw;
        acci += f.x*bw + f.y*a;
    }
    g_O[(size_t)(b*CC + o) * (MM*KY) + mk] = make_float2(accr, acci);
}

// ---------------- D: inverse x-DFT ----------------
// grid B*C, block 288 (thread = x)
__global__ void __launch_bounds__(288) k_ixdft() {
    __shared__ float2 sO[MM*KY];
    int bc = blockIdx.x, t = threadIdx.x;
    if (t < MM*KY) sO[t] = g_O[(size_t)bc * MM * KY + t];
    __syncthreads();
    float2 acc[KY];
    #pragma unroll
    for (int q = 0; q < KY; q++) acc[q] = make_float2(0.0f, 0.0f);
    #pragma unroll 4
    for (int m = 0; m < MM; m++) {
        float2 e = g_Exi[m*HP + t];
        #pragma unroll
        for (int q = 0; q < KY; q++) {
            float2 o = sO[m*KY + q];
            acc[q].x += o.x*e.x - o.y*e.y;
            acc[q].y += o.x*e.y + o.y*e.x;
        }
    }
    float2* out = g_T + ((size_t)bc * HP + t) * KY;
    #pragma unroll
    for (int q = 0; q < KY; q++) out[q] = acc[q];
}

// ---------------- E: fused 1x1 conv + inverse y-DFT + bias + gelu ----------------
// grid B*HP (blk = b*HP + x), block 144 (thread handles y=2t, 2t+1)
__global__ void __launch_bounds__(144) k_layer(const float* __restrict__ hin,
                                               float* __restrict__ hout,
                                               const float* __restrict__ conv_w,
                                               const float* __restrict__ conv_b,
                                               int l, int dogelu) {
    __shared__ float  sh[CC*HP];
    __shared__ float2 sT[CC*KY];
    __shared__ float  scw[CC*CC];
    __shared__ float  scb[CC];
    int blk = blockIdx.x;
    int b = blk / HP, x = blk % HP;
    int t = threadIdx.x;
    const float* hb = hin + (size_t)b * CC * PLANE + (size_t)x * HP;
    for (int i = t; i < CC*HP; i += 144) {
        int c = i / HP, y = i % HP;
        sh[i] = hb[(size_t)c * PLANE + y];
    }
    for (int i = t; i < CC*KY; i += 144)
        sT[i] = g_T[((size_t)(b*CC + i/KY) * HP + x) * KY + (i % KY)];
    for (int i = t; i < CC*CC; i += 144) scw[i] = conv_w[l*CC*CC + i];
    if (t < CC) scb[t] = conv_b[l*CC + t];
    __syncthreads();

    int y0 = 2*t, y1 = y0 + 1;
    float a0[CC], a1[CC];
    #pragma unroll
    for (int i = 0; i < CC; i++) { a0[i] = sh[i*HP + y0]; a1[i] = sh[i*HP + y1]; }
    float c0[KY], s0[KY], c1[KY], s1[KY];
    #pragma unroll
    for (int q = 0; q < KY; q++) {
        c0[q] = g_ICy[q*HP + y0]; s0[q] = g_ISy[q*HP + y0];
        c1[q] = g_ICy[q*HP + y1]; s1[q] = g_ISy[q*HP + y1];
    }
    float* ho = hout + (size_t)b * CC * PLANE + (size_t)x * HP;
    #pragma unroll 1
    for (int o = 0; o < CC; o++) {
        float v0 = scb[o], v1 = scb[o];
        #pragma unroll
        for (int i = 0; i < CC; i++) {
            float w = scw[o*CC + i];
            v0 += w * a0[i];
            v1 += w * a1[i];
        }
        #pragma unroll
        for (int q = 0; q < KY; q++) {
            float2 tq = sT[o*KY + q];
            v0 += tq.x*c0[q] - tq.y*s0[q];
            v1 += tq.x*c1[q] - tq.y*s1[q];
        }
        if (dogelu) { v0 = gelu_exact(v0); v1 = gelu_exact(v1); }
        reinterpret_cast<float2*>(ho + (size_t)o * PLANE)[t] = make_float2(v0, v1);
    }
}

// ---------------- final MLP 32 -> 128 (gelu) -> 2 ----------------
// grid B*SS (blk = b*256 + i), block 256 (thread = j)
__global__ void __launch_bounds__(256) k_mlp(const float* __restrict__ hin,
                                             const float* __restrict__ w1,
                                             const float* __restrict__ b1,
                                             const float* __restrict__ w2,
                                             const float* __restrict__ b2) {
    __shared__ float4 sw1[128*8];
    __shared__ float  sb1[128];
    __shared__ float  sw2[256];
    int t = threadIdx.x;
    for (int i = t; i < 1024; i += 256) sw1[i] = reinterpret_cast<const float4*>(w1)[i];
    if (t < 128) sb1[t] = b1[t];
    sw2[t] = w2[t];
    __syncthreads();
    int blk = blockIdx.x;
    int b = blk >> 8, ii = blk & 255;
    float u[CC];
    const float* hb = hin + (size_t)b * CC * PLANE + (size_t)ii * HP + t;
    #pragma unroll
    for (int c = 0; c < CC; c++) u[c] = hb[(size_t)c * PLANE];
    float d0 = 0.0f, d1 = 0.0f;
    #pragma unroll 2
    for (int k = 0; k < 128; k++) {
        float z = sb1[k];
        #pragma unroll
        for (int q = 0; q < 8; q++) {
            float4 w = sw1[k*8 + q];
            z += w.x*u[4*q] + w.y*u[4*q+1] + w.z*u[4*q+2] + w.w*u[4*q+3];
        }
        z = gelu_exact(z);
        d0 += sw2[k]       * z;
        d1 += sw2[128 + k] * z;
    }
    int p = ii*SS + t;
    g_tmp[(size_t)(b*2    ) * SS*SS + p] = d0 + __ldg(&b2[0]);
    g_tmp[(size_t)(b*2 + 1) * SS*SS + p] = d1 + __ldg(&b2[1]);
}

// ---------------- output permutation ----------------
__global__ void k_scatter(const int* __restrict__ v2d, float* __restrict__ out) {
    int idx = blockIdx.x * blockDim.x + threadIdx.x;
    if (idx >= BB*SS*SS) return;
    int b = idx >> 16, n = idx & 65535;
    int p = v2d[n];
    float v0 = g_tmp[(size_t)(b*2    ) * SS*SS + p];
    float v1 = g_tmp[(size_t)(b*2 + 1) * SS*SS + p];
    reinterpret_cast<float2*>(out)[idx] = make_float2(v0, v1);
}

// ---------------- launch ----------------
extern "C" void kernel_launch(void* const* d_in, const int* in_sizes, int n_in,
                              void* d_out, int out_size) {
    const float* x    = (const float*)d_in[0];
    const int*   d2v  = (const int*)  d_in[1];
    const int*   v2d  = (const int*)  d_in[2];
    const float* fc0w = (const float*)d_in[3];
    const float* fc0b = (const float*)d_in[4];
    const float* w1r  = (const float*)d_in[5];
    const float* w1i  = (const float*)d_in[6];
    const float* w2r  = (const float*)d_in[7];
    const float* w2i  = (const float*)d_in[8];
    const float* cw   = (const float*)d_in[9];
    const float* cb   = (const float*)d_in[10];
    const float* mw1  = (const float*)d_in[11];
    const float* mb1  = (const float*)d_in[12];
    const float* mw2  = (const float*)d_in[13];
    const float* mb2  = (const float*)d_in[14];

    float *h0, *h1;
    cudaGetSymbolAddress((void**)&h0, g_h0);
    cudaGetSymbolAddress((void**)&h1, g_h1);

    k_basis<<<(MM*HP + 255)/256, 256>>>();
    k_transw<<<(NLAY*MM*KY*CC*CC + 255)/256, 256>>>(w1r, w1i, w2r, w2i);
    k_embed<<<(BB*PLANE + 255)/256, 256>>>(x, d2v, fc0w, fc0b, h0);

    float* cur = h0;
    float* nxt = h1;
    for (int l = 0; l < NLAY; l++) {
        k_ydft<<<dim3(BB*CC, HP/16), 128>>>(cur);
        k_xdft<<<BB*CC, 288>>>();
        k_mix<<<BB*MM*KY, 32>>>(l);
        k_ixdft<<<BB*CC, 288>>>();
        k_layer<<<BB*HP, 144>>>(cur, nxt, cw, cb, l, (l < NLAY-1) ? 1 : 0);
        float* tp = cur; cur = nxt; nxt = tp;
    }
    k_mlp<<<BB*SS, 256>>>(cur, mw1, mb1, mw2, mb2);
    k_scatter<<<(BB*SS*SS + 255)/256, 256>>>(v2d, (float*)d_out);
}

// round 2
// speedup vs baseline: 1.0567x; 1.0567x over previous
#include <cuda_runtime.h>
#include <math.h>

#define BB 8
#define CC 32
#define SS 256
#define HP 288
#define KY 12
#define MM 24
#define NLAY 4
#define PLANE (HP*HP)

typedef unsigned long long ull;

// ---------------- packed fp32x2 helpers (Blackwell) ----------------
__device__ __forceinline__ ull pk(float lo, float hi) {
    ull r; asm("mov.b64 %0,{%1,%2};" : "=l"(r) : "f"(lo), "f"(hi)); return r;
}
__device__ __forceinline__ ull dup2(float v) { return pk(v, v); }
__device__ __forceinline__ void upk(float& lo, float& hi, ull v) {
    asm("mov.b64 {%0,%1},%2;" : "=f"(lo), "=f"(hi) : "l"(v));
}
__device__ __forceinline__ ull f2fma(ull a, ull b, ull c) {
    ull d; asm("fma.rn.f32x2 %0,%1,%2,%3;" : "=l"(d) : "l"(a), "l"(b), "l"(c)); return d;
}
__device__ __forceinline__ ull f2add(ull a, ull b) {
    ull d; asm("add.rn.f32x2 %0,%1,%2;" : "=l"(d) : "l"(a), "l"(b)); return d;
}

// ---------------- device scratch (static, no allocation) ----------------
__device__ float  g_h0[BB*CC*PLANE];
__device__ float  g_h1[BB*CC*PLANE];
__device__ float2 g_G [BB*CC*HP*KY];
__device__ float2 g_F [BB*CC*MM*KY];
__device__ float2 g_O [BB*CC*MM*KY];
__device__ float2 g_T [BB*CC*HP*KY];
__device__ float  g_Wtr[NLAY*MM*KY*CC*CC];
__device__ float  g_Wti[NLAY*MM*KY*CC*CC];
__device__ float2 g_Ey [KY*HP];   // [ky][y]  {cos, -sin}
__device__ float2 g_Ex [MM*HP];   // [m][x]   e^{-i...}
__device__ float2 g_Exi[MM*HP];   // [m][x]   e^{+i...}
__device__ float  g_ICy[KY*HP];   // alpha*cos/(288^2)
__device__ float  g_ISy[KY*HP];   // alpha*sin/(288^2)
__device__ float  g_tmp[BB*2*SS*SS];

__device__ __forceinline__ float gelu_exact(float x) {
    return 0.5f * x * (1.0f + erff(x * 0.70710678118654752440f));
}

// ---------------- basis tables ----------------
__global__ void k_basis() {
    int idx = blockIdx.x * blockDim.x + threadIdx.x;
    if (idx < KY*HP) {
        int ky = idx / HP, y = idx % HP;
        int r = (ky * y) % HP;
        float a = 6.28318530717958647692f * (float)r / (float)HP;
        float c = cosf(a), s = sinf(a);
        g_Ey[idx] = make_float2(c, -s);
        float al = (ky == 0) ? 1.0f : 2.0f;
        float inv = 1.0f / ((float)HP * (float)HP);
        g_ICy[idx] = al * inv * c;
        g_ISy[idx] = al * inv * s;
    }
    if (idx < MM*HP) {
        int m = idx / HP, xx = idx % HP;
        int kx = (m < KY) ? m : (264 + m);
        int r = (kx * xx) % HP;
        float a = 6.28318530717958647692f * (float)r / (float)HP;
        float c = cosf(a), s = sinf(a);
        g_Ex[idx]  = make_float2(c, -s);
        g_Exi[idx] = make_float2(c,  s);
    }
}

// ---------------- weight transpose: [l][i][o][kx][ky] -> [l][m][ky][i][o] ----------------
__global__ void k_transw(const float* __restrict__ w1r, const float* __restrict__ w1i,
                         const float* __restrict__ w2r, const float* __restrict__ w2i) {
    int idx = blockIdx.x * blockDim.x + threadIdx.x;
    if (idx >= NLAY*MM*KY*CC*CC) return;
    int o  = idx & 31;
    int i  = (idx >> 5) & 31;
    int ky = (idx >> 10) % KY;
    int rest = idx / (1024 * KY);
    int m = rest % MM;
    int l = rest / MM;
    const float *sr, *si;
    int src;
    if (m < KY) {
        src = (((l*CC + i)*CC + o)*12 + m)*12 + ky;
        sr = w1r; si = w1i;
    } else {
        src = (((l*CC + i)*CC + o)*12 + (m - 12))*12 + ky;
        sr = w2r; si = w2i;
    }
    g_Wtr[idx] = sr[src];
    g_Wti[idx] = si[src];
}

// ---------------- stage 0: gather + grid + fc0 (3->32), zero pad ----------------
__global__ void k_embed(const float* __restrict__ xin, const int* __restrict__ d2v,
                        const float* __restrict__ fw, const float* __restrict__ fb,
                        float* __restrict__ hout) {
    int idx = blockIdx.x * blockDim.x + threadIdx.x;
    if (idx >= BB*PLANE) return;
    int b = idx / PLANE;
    int rem = idx % PLANE;
    int i = rem / HP, j = rem % HP;
    float* hp = hout + (size_t)b * CC * PLANE + rem;
    if (i < SS && j < SS) {
        float v  = xin[b*SS*SS + d2v[i*SS + j]];
        float gi = (float)i * (1.0f/255.0f);
        float gj = (float)j * (1.0f/255.0f);
        #pragma unroll
        for (int c = 0; c < CC; c++)
            hp[(size_t)c*PLANE] = fw[c*3]*v + fw[c*3+1]*gi + fw[c*3+2]*gj + fb[c];
    } else {
        #pragma unroll
        for (int c = 0; c < CC; c++) hp[(size_t)c*PLANE] = 0.0f;
    }
}

// ---------------- A: truncated y-DFT, register-tiled, f32x2 ----------------
// grid B*C, block 288; thread t: rows (2g, 2g+1), half = ky group of 6
__global__ void __launch_bounds__(288) k_ydft(const float* __restrict__ h) {
    __shared__ __align__(16) float2 sEy[KY*HP];
    int t = threadIdx.x;
    for (int i = t; i < KY*HP; i += 288) sEy[i] = g_Ey[i];
    __syncthreads();
    int bc = blockIdx.x;
    int g = t >> 1, half = t & 1;
    const float4* r0 = (const float4*)(h + (size_t)bc * PLANE + (size_t)(2*g)   * HP);
    const float4* r1 = (const float4*)(h + (size_t)bc * PLANE + (size_t)(2*g+1) * HP);
    const ull* eb = (const ull*)(sEy + half * 6 * HP);
    ull acc0[6], acc1[6];
    #pragma unroll
    for (int q = 0; q < 6; q++) { acc0[q] = 0ull; acc1[q] = 0ull; }
    for (int yb = 0; yb < HP/4; yb++) {
        float4 va = r0[yb], vb = r1[yb];
        float aw[4] = {va.x, va.y, va.z, va.w};
        float bw[4] = {vb.x, vb.y, vb.z, vb.w};
        #pragma unroll
        for (int k = 0; k < 4; k++) {
            int y = 4*yb + k;
            ull ha = dup2(aw[k]);
            ull hb = dup2(bw[k]);
            #pragma unroll
            for (int q = 0; q < 6; q++) {
                ull e = eb[q*HP + y];
                acc0[q] = f2fma(ha, e, acc0[q]);
                acc1[q] = f2fma(hb, e, acc1[q]);
            }
        }
    }
    float2* out0 = g_G + ((size_t)bc * HP + 2*g    ) * KY + half*6;
    float2* out1 = g_G + ((size_t)bc * HP + 2*g + 1) * KY + half*6;
    #pragma unroll
    for (int q = 0; q < 6; q++) {
        float lo, hi;
        upk(lo, hi, acc0[q]); out0[q] = make_float2(lo, hi);
        upk(lo, hi, acc1[q]); out1[q] = make_float2(lo, hi);
    }
}

// ---------------- B: x-DFT onto 24 modes ----------------
__global__ void __launch_bounds__(288) k_xdft() {
    __shared__ float2 sG[HP*KY];
    int bc = blockIdx.x, t = threadIdx.x;
    const float2* Gp = g_G + (size_t)bc * HP * KY;
    for (int i = t; i < HP*KY; i += 288) sG[i] = Gp[i];
    __syncthreads();
    int m = t / KY, ky = t % KY;
    float accx = 0.0f, accy = 0.0f;
    const float2* ex = g_Ex + m * HP;
    for (int x = 0; x < HP; x++) {
        float2 g = sG[x*KY + ky];
        float2 e = ex[x];
        accx += g.x*e.x - g.y*e.y;
        accy += g.x*e.y + g.y*e.x;
    }
    g_F[((size_t)bc * MM + m) * KY + ky] = make_float2(accx, accy);
}

// ---------------- C: complex channel mix ----------------
__global__ void k_mix(int l) {
    int blk = blockIdx.x;
    int b  = blk / (MM*KY);
    int mk = blk % (MM*KY);
    int o = threadIdx.x;
    __shared__ float2 sF[CC];
    sF[o] = g_F[(size_t)(b*CC + o) * (MM*KY) + mk];
    __syncthreads();
    const float* wr = g_Wtr + ((size_t)l * MM * KY + mk) * CC * CC;
    const float* wi = g_Wti + ((size_t)l * MM * KY + mk) * CC * CC;
    float accr = 0.0f, acci = 0.0f;
    #pragma unroll 4
    for (int i = 0; i < CC; i++) {
        float2 f = sF[i];
        float a = wr[i*CC + o], bw = wi[i*CC + o];
        accr += f.x*a  - f.y*bw;
        acci += f.x*bw + f.y*a;
    }
    g_O[(size_t)(b*CC + o) * (MM*KY) + mk] = make_float2(accr, acci);
}

// ---------------- D: inverse x-DFT ----------------
__global__ void __launch_bounds__(288) k_ixdft() {
    __shared__ float2 sO[MM*KY];
    int bc = blockIdx.x, t = threadIdx.x;
    if (t < MM*KY) sO[t] = g_O[(size_t)bc * MM * KY + t];
    __syncthreads();
    float2 acc[KY];
    #pragma unroll
    for (int q = 0; q < KY; q++) acc[q] = make_float2(0.0f, 0.0f);
    #pragma unroll 4
    for (int m = 0; m < MM; m++) {
        float2 e = g_Exi[m*HP + t];
        #pragma unroll
        for (int q = 0; q < KY; q++) {
            float2 o = sO[m*KY + q];
            acc[q].x += o.x*e.x - o.y*e.y;
            acc[q].y += o.x*e.y + o.y*e.x;
        }
    }
    float2* out = g_T + ((size_t)bc * HP + t) * KY;
    #pragma unroll
    for (int q = 0; q < KY; q++) out[q] = acc[q];
}

// ---------------- E: fused 1x1 conv + inverse y-DFT + bias + gelu, f32x2 ----------------
// grid B*HP (blk = b*HP + x), block 144 (thread = y pair)
__global__ void __launch_bounds__(144) k_layer(const float* __restrict__ hin,
                                               float* __restrict__ hout,
                                               const float* __restrict__ conv_w,
                                               const float* __restrict__ conv_b,
                                               int l, int dogelu) {
    __shared__ __align__(16) ull sW[CC*CC];    // [o][i] = {w,w}
    __shared__ __align__(16) ull sTr[CC*KY];   // [o][q] = {Tr,Tr}
    __shared__ __align__(16) ull sTi[CC*KY];   // [o][q] = {-Ti,-Ti}
    __shared__ float scb[CC];
    int blk = blockIdx.x;
    int b = blk / HP, x = blk % HP;
    int t = threadIdx.x;
    for (int i = t; i < CC*CC; i += 144) {
        float w = conv_w[l*CC*CC + i];
        sW[i] = dup2(w);
    }
    for (int i = t; i < CC*KY; i += 144) {
        float2 v = g_T[((size_t)(b*CC + i/KY) * HP + x) * KY + (i % KY)];
        sTr[i] = dup2(v.x);
        sTi[i] = dup2(-v.y);
    }
    if (t < CC) scb[t] = conv_b[l*CC + t];
    __syncthreads();

    int y0 = 2*t;
    const float* hb = hin + (size_t)b * CC * PLANE + (size_t)x * HP + y0;
    ull h2[CC];
    #pragma unroll
    for (int i = 0; i < CC; i++)
        h2[i] = *(const ull*)(hb + (size_t)i * PLANE);
    ull c2[KY], s2[KY];
    #pragma unroll
    for (int q = 0; q < KY; q++) {
        c2[q] = *(const ull*)(g_ICy + q*HP + y0);
        s2[q] = *(const ull*)(g_ISy + q*HP + y0);
    }
    float* ho = hout + (size_t)b * CC * PLANE + (size_t)x * HP + y0;
    #pragma unroll 1
    for (int o = 0; o < CC; o++) {
        const ulonglong2* w2  = (const ulonglong2*)(sW  + o*CC);
        const ulonglong2* tr2 = (const ulonglong2*)(sTr + o*KY);
        const ulonglong2* ti2 = (const ulonglong2*)(sTi + o*KY);
        ull a[4];
        a[0] = dup2(scb[o]); a[1] = 0ull; a[2] = 0ull; a[3] = 0ull;
        #pragma unroll
        for (int j = 0; j < CC/2; j++) {
            ulonglong2 wp = w2[j];
            a[(2*j)   & 3] = f2fma(wp.x, h2[2*j],   a[(2*j)   & 3]);
            a[(2*j+1) & 3] = f2fma(wp.y, h2[2*j+1], a[(2*j+1) & 3]);
        }
        ull b0 = 0ull, b1 = 0ull, b2 = 0ull, b3 = 0ull;
        #pragma unroll
        for (int j = 0; j < KY/2; j++) {
            ulonglong2 tp = tr2[j];
            ulonglong2 ip = ti2[j];
            b0 = f2fma(tp.x, c2[2*j],   b0);
            b1 = f2fma(tp.y, c2[2*j+1], b1);
            b2 = f2fma(ip.x, s2[2*j],   b2);
            b3 = f2fma(ip.y, s2[2*j+1], b3);
        }
        ull sm = f2add(f2add(a[0], a[1]), f2add(a[2], a[3]));
        sm = f2add(sm, f2add(f2add(b0, b1), f2add(b2, b3)));
        float v0, v1;
        upk(v0, v1, sm);
        if (dogelu) { v0 = gelu_exact(v0); v1 = gelu_exact(v1); }
        *(float2*)(ho + (size_t)o * PLANE) = make_float2(v0, v1);
    }
}

// ---------------- final MLP 32 -> 128 (gelu) -> 2, f32x2 ----------------
__global__ void __launch_bounds__(256) k_mlp(const float* __restrict__ hin,
                                             const float* __restrict__ w1,
                                             const float* __restrict__ b1,
                                             const float* __restrict__ w2,
                                             const float* __restrict__ b2) {
    __shared__ __align__(16) ull sw[64*CC];   // [k2][i] = {w1[2k2,i], w1[2k2+1,i]}
    __shared__ ull sb[64];
    __shared__ float so0[128], so1[128];
    int t = threadIdx.x;
    for (int idx = t; idx < 64*CC; idx += 256) {
        int k2 = idx >> 5, i = idx & 31;
        sw[idx] = pk(w1[(2*k2)*CC + i], w1[(2*k2+1)*CC + i]);
    }
    if (t < 64) sb[t] = pk(b1[2*t], b1[2*t+1]);
    if (t < 128) { so0[t] = w2[t]; so1[t] = w2[128 + t]; }
    __syncthreads();
    int blk = blockIdx.x;
    int b = blk >> 8, ii = blk & 255;
    const float* hb = hin + (size_t)b * CC * PLANE + (size_t)ii * HP + t;
    ull u2[CC];
    #pragma unroll
    for (int c = 0; c < CC; c++) u2[c] = dup2(hb[(size_t)c * PLANE]);
    float d0 = 0.0f, d1 = 0.0f;
    #pragma unroll 1
    for (int k2 = 0; k2 < 64; k2++) {
        const ulonglong2* wp = (const ulonglong2*)(sw + k2*CC);
        ull za = sb[k2], zb = 0ull, zc = 0ull, zd = 0ull;
        #pragma unroll
        for (int j = 0; j < CC/2; j++) {
            ulonglong2 w = wp[j];
            if (j & 1) { zc = f2fma(w.x, u2[2*j], zc); zd = f2fma(w.y, u2[2*j+1], zd); }
            else       { za = f2fma(w.x, u2[2*j], za); zb = f2fma(w.y, u2[2*j+1], zb); }
        }
        ull z2 = f2add(f2add(za, zb), f2add(zc, zd));
        float z0, z1;
        upk(z0, z1, z2);
        z0 = gelu_exact(z0);
        z1 = gelu_exact(z1);
        d0 += so0[2*k2]*z0 + so0[2*k2+1]*z1;
        d1 += so1[2*k2]*z0 + so1[2*k2+1]*z1;
    }
    int p = ii*SS + t;
    g_tmp[(size_t)(b*2    ) * SS*SS + p] = d0 + __ldg(&b2[0]);
    g_tmp[(size_t)(b*2 + 1) * SS*SS + p] = d1 + __ldg(&b2[1]);
}

// ---------------- output permutation ----------------
__global__ void k_scatter(const int* __restrict__ v2d, float* __restrict__ out) {
    int idx = blockIdx.x * blockDim.x + threadIdx.x;
    if (idx >= BB*SS*SS) return;
    int b = idx >> 16, n = idx & 65535;
    int p = v2d[n];
    float v0 = g_tmp[(size_t)(b*2    ) * SS*SS + p];
    float v1 = g_tmp[(size_t)(b*2 + 1) * SS*SS + p];
    reinterpret_cast<float2*>(out)[idx] = make_float2(v0, v1);
}

// ---------------- launch ----------------
extern "C" void kernel_launch(void* const* d_in, const int* in_sizes, int n_in,
                              void* d_out, int out_size) {
    const float* x    = (const float*)d_in[0];
    const int*   d2v  = (const int*)  d_in[1];
    const int*   v2d  = (const int*)  d_in[2];
    const float* fc0w = (const float*)d_in[3];
    const float* fc0b = (const float*)d_in[4];
    const float* w1r  = (const float*)d_in[5];
    const float* w1i  = (const float*)d_in[6];
    const float* w2r  = (const float*)d_in[7];
    const float* w2i  = (const float*)d_in[8];
    const float* cw   = (const float*)d_in[9];
    const float* cb   = (const float*)d_in[10];
    const float* mw1  = (const float*)d_in[11];
    const float* mb1  = (const float*)d_in[12];
    const float* mw2  = (const float*)d_in[13];
    const float* mb2  = (const float*)d_in[14];

    float *h0, *h1;
    cudaGetSymbolAddress((void**)&h0, g_h0);
    cudaGetSymbolAddress((void**)&h1, g_h1);

    k_basis<<<(MM*HP + 255)/256, 256>>>();
    k_transw<<<(NLAY*MM*KY*CC*CC + 255)/256, 256>>>(w1r, w1i, w2r, w2i);
    k_embed<<<(BB*PLANE + 255)/256, 256>>>(x, d2v, fc0w, fc0b, h0);

    float* cur = h0;
    float* nxt = h1;
    for (int l = 0; l < NLAY; l++) {
        k_ydft<<<BB*CC, 288>>>(cur);
        k_xdft<<<BB*CC, 288>>>();
        k_mix<<<BB*MM*KY, 32>>>(l);
        k_ixdft<<<BB*CC, 288>>>();
        k_layer<<<BB*HP, 144>>>(cur, nxt, cw, cb, l, (l < NLAY-1) ? 1 : 0);
        float* tp = cur; cur = nxt; nxt = tp;
    }
    k_mlp<<<BB*SS, 256>>>(cur, mw1, mb1, mw2, mb2);
    k_scatter<<<(BB*SS*SS + 255)/256, 256>>>(v2d, (float*)d_out);
}

// round 3
// speedup vs baseline: 1.2169x; 1.1516x over previous
#include <cuda_runtime.h>
#include <math.h>

#define BB 8
#define CC 32
#define SS 256
#define HP 288
#define KY 12
#define MM 24
#define NLAY 4
#define PLANE (HP*HP)

typedef unsigned long long ull;

// ---------------- packed fp32x2 helpers ----------------
__device__ __forceinline__ ull pk(float lo, float hi) {
    ull r; asm("mov.b64 %0,{%1,%2};" : "=l"(r) : "f"(lo), "f"(hi)); return r;
}
__device__ __forceinline__ ull dup2(float v) { return pk(v, v); }
__device__ __forceinline__ void upk(float& lo, float& hi, ull v) {
    asm("mov.b64 {%0,%1},%2;" : "=f"(lo), "=f"(hi) : "l"(v));
}
__device__ __forceinline__ ull f2fma(ull a, ull b, ull c) {
    ull d; asm("fma.rn.f32x2 %0,%1,%2,%3;" : "=l"(d) : "l"(a), "l"(b), "l"(c)); return d;
}
__device__ __forceinline__ ull f2add(ull a, ull b) {
    ull d; asm("add.rn.f32x2 %0,%1,%2;" : "=l"(d) : "l"(a), "l"(b)); return d;
}

// ---------------- tf32 mma helpers ----------------
__device__ __forceinline__ unsigned f2tf(float x) {
    unsigned r; asm("cvt.rna.tf32.f32 %0,%1;" : "=r"(r) : "f"(x)); return r;
}
__device__ __forceinline__ void tfsplit(float x, unsigned& hi, unsigned& lo) {
    hi = f2tf(x);
    float res = x - __uint_as_float(hi);
    lo = f2tf(res);
}
__device__ __forceinline__ void mma_tf32(float c[4],
    unsigned a0, unsigned a1, unsigned a2, unsigned a3,
    unsigned b0, unsigned b1) {
    asm volatile(
        "mma.sync.aligned.m16n8k8.row.col.f32.tf32.tf32.f32 "
        "{%0,%1,%2,%3},{%4,%5,%6,%7},{%8,%9},{%0,%1,%2,%3};"
        : "+f"(c[0]), "+f"(c[1]), "+f"(c[2]), "+f"(c[3])
        : "r"(a0), "r"(a1), "r"(a2), "r"(a3), "r"(b0), "r"(b1));
}

// ---------------- device scratch ----------------
__device__ float  g_h0[BB*CC*PLANE];
__device__ float  g_h1[BB*CC*PLANE];
__device__ float2 g_G [BB*CC*HP*KY];
__device__ float2 g_F [BB*CC*MM*KY];
__device__ float2 g_O [BB*CC*MM*KY];
__device__ float2 g_T [BB*CC*HP*KY];
__device__ float  g_Wtr[NLAY*MM*KY*CC*CC];
__device__ float  g_Wti[NLAY*MM*KY*CC*CC];
__device__ float2 g_Ey [KY*HP];
__device__ float2 g_Ex [MM*HP];
__device__ float2 g_Exi[MM*HP];
__device__ float  g_ICy[KY*HP];
__device__ float  g_ISy[KY*HP];
__device__ float  g_tmp[BB*2*SS*SS];

__device__ __forceinline__ float gelu_exact(float x) {
    return 0.5f * x * (1.0f + erff(x * 0.70710678118654752440f));
}

// ---------------- basis tables ----------------
__global__ void k_basis() {
    int idx = blockIdx.x * blockDim.x + threadIdx.x;
    if (idx < KY*HP) {
        int ky = idx / HP, y = idx % HP;
        int r = (ky * y) % HP;
        float a = 6.28318530717958647692f * (float)r / (float)HP;
        float c = cosf(a), s = sinf(a);
        g_Ey[idx] = make_float2(c, -s);
        float al = (ky == 0) ? 1.0f : 2.0f;
        float inv = 1.0f / ((float)HP * (float)HP);
        g_ICy[idx] = al * inv * c;
        g_ISy[idx] = al * inv * s;
    }
    if (idx < MM*HP) {
        int m = idx / HP, xx = idx % HP;
        int kx = (m < KY) ? m : (264 + m);
        int r = (kx * xx) % HP;
        float a = 6.28318530717958647692f * (float)r / (float)HP;
        float c = cosf(a), s = sinf(a);
        g_Ex[idx]  = make_float2(c, -s);
        g_Exi[idx] = make_float2(c,  s);
    }
}

// ---------------- weight transpose ----------------
__global__ void k_transw(const float* __restrict__ w1r, const float* __restrict__ w1i,
                         const float* __restrict__ w2r, const float* __restrict__ w2i) {
    int idx = blockIdx.x * blockDim.x + threadIdx.x;
    if (idx >= NLAY*MM*KY*CC*CC) return;
    int o  = idx & 31;
    int i  = (idx >> 5) & 31;
    int ky = (idx >> 10) % KY;
    int rest = idx / (1024 * KY);
    int m = rest % MM;
    int l = rest / MM;
    const float *sr, *si;
    int src;
    if (m < KY) {
        src = (((l*CC + i)*CC + o)*12 + m)*12 + ky;
        sr = w1r; si = w1i;
    } else {
        src = (((l*CC + i)*CC + o)*12 + (m - 12))*12 + ky;
        sr = w2r; si = w2i;
    }
    g_Wtr[idx] = sr[src];
    g_Wti[idx] = si[src];
}

// ---------------- stage 0: embed ----------------
__global__ void k_embed(const float* __restrict__ xin, const int* __restrict__ d2v,
                        const float* __restrict__ fw, const float* __restrict__ fb,
                        float* __restrict__ hout) {
    int idx = blockIdx.x * blockDim.x + threadIdx.x;
    if (idx >= BB*PLANE) return;
    int b = idx / PLANE;
    int rem = idx % PLANE;
    int i = rem / HP, j = rem % HP;
    float* hp = hout + (size_t)b * CC * PLANE + rem;
    if (i < SS && j < SS) {
        float v  = xin[b*SS*SS + d2v[i*SS + j]];
        float gi = (float)i * (1.0f/255.0f);
        float gj = (float)j * (1.0f/255.0f);
        #pragma unroll
        for (int c = 0; c < CC; c++)
            hp[(size_t)c*PLANE] = fw[c*3]*v + fw[c*3+1]*gi + fw[c*3+2]*gj + fb[c];
    } else {
        #pragma unroll
        for (int c = 0; c < CC; c++) hp[(size_t)c*PLANE] = 0.0f;
    }
}

// ---------------- A: truncated y-DFT, 4 x-slices, f32x2 ----------------
// grid (B*C, 4), block 288; thread: row = slice*72 + t>>2, quarter = t&3 (3 modes)
__global__ void __launch_bounds__(288) k_ydft(const float* __restrict__ h) {
    __shared__ __align__(16) float2 sEy[KY*292];
    int t = threadIdx.x;
    for (int i = t; i < KY*HP; i += 288) {
        int ky = i / HP, y = i % HP;
        sEy[ky*292 + y] = g_Ey[i];
    }
    __syncthreads();
    int bc = blockIdx.x;
    int row = blockIdx.y * 72 + (t >> 2);
    int quarter = t & 3;
    const float4* rp = (const float4*)(h + (size_t)bc * PLANE + (size_t)row * HP);
    const ull* eb = (const ull*)(sEy + quarter * 3 * 292);
    ull acc[3];
    acc[0] = 0ull; acc[1] = 0ull; acc[2] = 0ull;
    #pragma unroll 4
    for (int yb = 0; yb < 72; yb++) {
        float4 v = rp[yb];
        int y = 4*yb;
        float vw[4] = {v.x, v.y, v.z, v.w};
        #pragma unroll
        for (int k = 0; k < 4; k++) {
            ull hv = dup2(vw[k]);
            #pragma unroll
            for (int q = 0; q < 3; q++)
                acc[q] = f2fma(hv, eb[q*292 + y + k], acc[q]);
        }
    }
    float2* out = g_G + ((size_t)bc * HP + row) * KY + quarter * 3;
    #pragma unroll
    for (int q = 0; q < 3; q++) {
        float lo, hi;
        upk(lo, hi, acc[q]);
        out[q] = make_float2(lo, hi);
    }
}

// ---------------- B: x-DFT onto 24 modes ----------------
__global__ void __launch_bounds__(288) k_xdft() {
    __shared__ float2 sG[HP*KY];
    int bc = blockIdx.x, t = threadIdx.x;
    const float2* Gp = g_G + (size_t)bc * HP * KY;
    for (int i = t; i < HP*KY; i += 288) sG[i] = Gp[i];
    __syncthreads();
    int m = t / KY, ky = t % KY;
    float accx = 0.0f, accy = 0.0f;
    const float2* ex = g_Ex + m * HP;
    for (int x = 0; x < HP; x++) {
        float2 g = sG[x*KY + ky];
        float2 e = ex[x];
        accx += g.x*e.x - g.y*e.y;
        accy += g.x*e.y + g.y*e.x;
    }
    g_F[((size_t)bc * MM + m) * KY + ky] = make_float2(accx, accy);
}

// ---------------- C: complex channel mix ----------------
__global__ void k_mix(int l) {
    int blk = blockIdx.x;
    int b  = blk / (MM*KY);
    int mk = blk % (MM*KY);
    int o = threadIdx.x;
    __shared__ float2 sF[CC];
    sF[o] = g_F[(size_t)(b*CC + o) * (MM*KY) + mk];
    __syncthreads();
    const float* wr = g_Wtr + ((size_t)l * MM * KY + mk) * CC * CC;
    const float* wi = g_Wti + ((size_t)l * MM * KY + mk) * CC * CC;
    float accr = 0.0f, acci = 0.0f;
    #pragma unroll 4
    for (int i = 0; i < CC; i++) {
        float2 f = sF[i];
        float a = wr[i*CC + o], bw = wi[i*CC + o];
        accr += f.x*a  - f.y*bw;
        acci += f.x*bw + f.y*a;
    }
    g_O[(size_t)(b*CC + o) * (MM*KY) + mk] = make_float2(accr, acci);
}

// ---------------- D: inverse x-DFT ----------------
__global__ void __launch_bounds__(288) k_ixdft() {
    __shared__ float2 sO[MM*KY];
    int bc = blockIdx.x, t = threadIdx.x;
    if (t < MM*KY) sO[t] = g_O[(size_t)bc * MM * KY + t];
    __syncthreads();
    float2 acc[KY];
    #pragma unroll
    for (int q = 0; q < KY; q++) acc[q] = make_float2(0.0f, 0.0f);
    #pragma unroll 4
    for (int m = 0; m < MM; m++) {
        float2 e = g_Exi[m*HP + t];
        #pragma unroll
        for (int q = 0; q < KY; q++) {
            float2 o = sO[m*KY + q];
            acc[q].x += o.x*e.x - o.y*e.y;
            acc[q].y += o.x*e.y + o.y*e.x;
        }
    }
    float2* out = g_T + ((size_t)bc * HP + t) * KY;
    #pragma unroll
    for (int q = 0; q < KY; q++) out[q] = acc[q];
}

// ---------------- E: fused conv + inverse y-DFT as one tf32 MMA GEMM ----------------
// out[32 x 288] = Wcat[32 x 56] * Hcat[56 x 288] per (b,x); 3xTF32 split.
// grid (B*HP, 2): blockIdx.y = y-half (144 cols). block 128 = 4 warps (2m x 2n).
#define HS 152   // Hcat smem row stride (144 + 8, conflict-free b-frag loads)
#define WS 68    // Wcat smem row stride
__global__ void __launch_bounds__(128) k_layer(const float* __restrict__ hin,
                                               float* __restrict__ hout,
                                               const float* __restrict__ conv_w,
                                               const float* __restrict__ conv_b,
                                               int l, int dogelu) {
    __shared__ __align__(16) float sH[56*HS];
    __shared__ float sW[32*WS];
    __shared__ float scb[CC];
    int blk = blockIdx.x;
    int b = blk / HP, x = blk % HP;
    int y0 = blockIdx.y * 144;
    int t = threadIdx.x;

    // build Hcat: rows 0..31 = h channels, 32..43 = ICy, 44..55 = ISy
    for (int idx = t; idx < 56*36; idx += 128) {
        int r = idx / 36, c4 = (idx % 36) * 4;
        float4 v;
        if (r < 32)
            v = *(const float4*)(hin + (size_t)(b*CC + r)*PLANE + (size_t)x*HP + y0 + c4);
        else if (r < 44)
            v = *(const float4*)(g_ICy + (r-32)*HP + y0 + c4);
        else
            v = *(const float4*)(g_ISy + (r-44)*HP + y0 + c4);
        *(float4*)(sH + r*HS + c4) = v;
    }
    // build Wcat: cols 0..31 = conv W, 32..43 = Tr, 44..55 = -Ti
    for (int idx = t; idx < 32*56; idx += 128) {
        int o = idx / 56, c = idx % 56;
        float w;
        if (c < 32)
            w = conv_w[l*CC*CC + o*CC + c];
        else if (c < 44)
            w = g_T[((size_t)(b*CC + o)*HP + x)*KY + (c-32)].x;
        else
            w = -g_T[((size_t)(b*CC + o)*HP + x)*KY + (c-44)].y;
        sW[o*WS + c] = w;
    }
    if (t < CC) scb[t] = conv_b[l*CC + t];
    __syncthreads();

    int wid = t >> 5, lane = t & 31;
    int warp_m = wid & 1, warp_n = wid >> 1;
    int lr = lane >> 2, lc = lane & 3;

    float acc[9][4];
    #pragma unroll
    for (int nt = 0; nt < 9; nt++)
        #pragma unroll
        for (int j = 0; j < 4; j++) acc[nt][j] = 0.0f;

    int row0 = warp_m*16 + lr;
    #pragma unroll
    for (int kb = 0; kb < 7; kb++) {
        int kk = kb*8 + lc;
        float a0f = sW[row0*WS + kk];
        float a1f = sW[(row0+8)*WS + kk];
        float a2f = sW[row0*WS + kk + 4];
        float a3f = sW[(row0+8)*WS + kk + 4];
        unsigned ah0, al0, ah1, al1, ah2, al2, ah3, al3;
        tfsplit(a0f, ah0, al0); tfsplit(a1f, ah1, al1);
        tfsplit(a2f, ah2, al2); tfsplit(a3f, ah3, al3);
        #pragma unroll
        for (int nt = 0; nt < 9; nt++) {
            int nb = warp_n*72 + nt*8 + lr;
            float b0f = sH[kk*HS + nb];
            float b1f = sH[(kk+4)*HS + nb];
            unsigned bh0, bl0, bh1, bl1;
            tfsplit(b0f, bh0, bl0);
            tfsplit(b1f, bh1, bl1);
            mma_tf32(acc[nt], ah0, ah1, ah2, ah3, bl0, bl1);
            mma_tf32(acc[nt], al0, al1, al2, al3, bh0, bh1);
            mma_tf32(acc[nt], ah0, ah1, ah2, ah3, bh0, bh1);
        }
    }

    int o0 = warp_m*16 + lr;
    float bia0 = scb[o0], bia1 = scb[o0 + 8];
    float* base0 = hout + (size_t)(b*CC + o0)*PLANE + (size_t)x*HP;
    float* base1 = hout + (size_t)(b*CC + o0 + 8)*PLANE + (size_t)x*HP;
    #pragma unroll
    for (int nt = 0; nt < 9; nt++) {
        int y = y0 + warp_n*72 + nt*8 + 2*lc;
        float v0 = acc[nt][0] + bia0, v1 = acc[nt][1] + bia0;
        float v2 = acc[nt][2] + bia1, v3 = acc[nt][3] + bia1;
        if (dogelu) {
            v0 = gelu_exact(v0); v1 = gelu_exact(v1);
            v2 = gelu_exact(v2); v3 = gelu_exact(v3);
        }
        *(float2*)(base0 + y) = make_float2(v0, v1);
        *(float2*)(base1 + y) = make_float2(v2, v3);
    }
}

// ---------------- final MLP 32 -> 128 (gelu) -> 2, f32x2 ----------------
__global__ void __launch_bounds__(256) k_mlp(const float* __restrict__ hin,
                                             const float* __restrict__ w1,
                                             const float* __restrict__ b1,
                                             const float* __restrict__ w2,
                                             const float* __restrict__ b2) {
    __shared__ __align__(16) ull sw[64*CC];
    __shared__ ull sb[64];
    __shared__ float so0[128], so1[128];
    int t = threadIdx.x;
    for (int idx = t; idx < 64*CC; idx += 256) {
        int k2 = idx >> 5, i = idx & 31;
        sw[idx] = pk(w1[(2*k2)*CC + i], w1[(2*k2+1)*CC + i]);
    }
    if (t < 64) sb[t] = pk(b1[2*t], b1[2*t+1]);
    if (t < 128) { so0[t] = w2[t]; so1[t] = w2[128 + t]; }
    __syncthreads();
    int blk = blockIdx.x;
    int b = blk >> 8, ii = blk & 255;
    const float* hb = hin + (size_t)b * CC * PLANE + (size_t)ii * HP + t;
    ull u2[CC];
    #pragma unroll
    for (int c = 0; c < CC; c++) u2[c] = dup2(hb[(size_t)c * PLANE]);
    float d0 = 0.0f, d1 = 0.0f;
    #pragma unroll 1
    for (int k2 = 0; k2 < 64; k2++) {
        const ulonglong2* wp = (const ulonglong2*)(sw + k2*CC);
        ull za = sb[k2], zb = 0ull, zc = 0ull, zd = 0ull;
        #pragma unroll
        for (int j = 0; j < CC/2; j++) {
            ulonglong2 w = wp[j];
            if (j & 1) { zc = f2fma(w.x, u2[2*j], zc); zd = f2fma(w.y, u2[2*j+1], zd); }
            else       { za = f2fma(w.x, u2[2*j], za); zb = f2fma(w.y, u2[2*j+1], zb); }
        }
        ull z2 = f2add(f2add(za, zb), f2add(zc, zd));
        float z0, z1;
        upk(z0, z1, z2);
        z0 = gelu_exact(z0);
        z1 = gelu_exact(z1);
        d0 += so0[2*k2]*z0 + so0[2*k2+1]*z1;
        d1 += so1[2*k2]*z0 + so1[2*k2+1]*z1;
    }
    int p = ii*SS + t;
    g_tmp[(size_t)(b*2    ) * SS*SS + p] = d0 + __ldg(&b2[0]);
    g_tmp[(size_t)(b*2 + 1) * SS*SS + p] = d1 + __ldg(&b2[1]);
}

// ---------------- output permutation ----------------
__global__ void k_scatter(const int* __restrict__ v2d, float* __restrict__ out) {
    int idx = blockIdx.x * blockDim.x + threadIdx.x;
    if (idx >= BB*SS*SS) return;
    int b = idx >> 16, n = idx & 65535;
    int p = v2d[n];
    float v0 = g_tmp[(size_t)(b*2    ) * SS*SS + p];
    float v1 = g_tmp[(size_t)(b*2 + 1) * SS*SS + p];
    reinterpret_cast<float2*>(out)[idx] = make_float2(v0, v1);
}

// ---------------- launch ----------------
extern "C" void kernel_launch(void* const* d_in, const int* in_sizes, int n_in,
                              void* d_out, int out_size) {
    const float* x    = (const float*)d_in[0];
    const int*   d2v  = (const int*)  d_in[1];
    const int*   v2d  = (const int*)  d_in[2];
    const float* fc0w = (const float*)d_in[3];
    const float* fc0b = (const float*)d_in[4];
    const float* w1r  = (const float*)d_in[5];
    const float* w1i  = (const float*)d_in[6];
    const float* w2r  = (const float*)d_in[7];
    const float* w2i  = (const float*)d_in[8];
    const float* cw   = (const float*)d_in[9];
    const float* cb   = (const float*)d_in[10];
    const float* mw1  = (const float*)d_in[11];
    const float* mb1  = (const float*)d_in[12];
    const float* mw2  = (const float*)d_in[13];
    const float* mb2  = (const float*)d_in[14];

    float *h0, *h1;
    cudaGetSymbolAddress((void**)&h0, g_h0);
    cudaGetSymbolAddress((void**)&h1, g_h1);

    k_basis<<<(MM*HP + 255)/256, 256>>>();
    k_transw<<<(NLAY*MM*KY*CC*CC + 255)/256, 256>>>(w1r, w1i, w2r, w2i);
    k_embed<<<(BB*PLANE + 255)/256, 256>>>(x, d2v, fc0w, fc0b, h0);

    float* cur = h0;
    float* nxt = h1;
    for (int l = 0; l < NLAY; l++) {
        k_ydft<<<dim3(BB*CC, 4), 288>>>(cur);
        k_xdft<<<BB*CC, 288>>>();
        k_mix<<<BB*MM*KY, 32>>>(l);
        k_ixdft<<<BB*CC, 288>>>();
        k_layer<<<dim3(BB*HP, 2), 128>>>(cur, nxt, cw, cb, l, (l < NLAY-1) ? 1 : 0);
        float* tp = cur; cur = nxt; nxt = tp;
    }
    k_mlp<<<BB*SS, 256>>>(cur, mw1, mb1, mw2, mb2);
    k_scatter<<<(BB*SS*SS + 255)/256, 256>>>(v2d, (float*)d_out);
}

// round 4
// speedup vs baseline: 1.3346x; 1.0968x over previous
#include <cuda_runtime.h>
#include <math.h>

#define BB 8
#define CC 32
#define SS 256
#define HP 288
#define KY 12
#define MM 24
#define NLAY 4
#define PLANE (HP*HP)

typedef unsigned long long ull;

// ---------------- packed fp32x2 helpers ----------------
__device__ __forceinline__ ull pk(float lo, float hi) {
    ull r; asm("mov.b64 %0,{%1,%2};" : "=l"(r) : "f"(lo), "f"(hi)); return r;
}
__device__ __forceinline__ ull dup2(float v) { return pk(v, v); }
__device__ __forceinline__ void upk(float& lo, float& hi, ull v) {
    asm("mov.b64 {%0,%1},%2;" : "=f"(lo), "=f"(hi) : "l"(v));
}
__device__ __forceinline__ ull f2fma(ull a, ull b, ull c) {
    ull d; asm("fma.rn.f32x2 %0,%1,%2,%3;" : "=l"(d) : "l"(a), "l"(b), "l"(c)); return d;
}
__device__ __forceinline__ ull f2add(ull a, ull b) {
    ull d; asm("add.rn.f32x2 %0,%1,%2;" : "=l"(d) : "l"(a), "l"(b)); return d;
}

// ---------------- tf32 mma helpers ----------------
__device__ __forceinline__ unsigned f2tf(float x) {
    unsigned r; asm("cvt.rna.tf32.f32 %0,%1;" : "=r"(r) : "f"(x)); return r;
}
__device__ __forceinline__ void tfsplit(float x, unsigned& hi, unsigned& lo) {
    hi = f2tf(x);
    float res = x - __uint_as_float(hi);
    lo = f2tf(res);
}
__device__ __forceinline__ void mma_tf32(float c[4],
    unsigned a0, unsigned a1, unsigned a2, unsigned a3,
    unsigned b0, unsigned b1) {
    asm volatile(
        "mma.sync.aligned.m16n8k8.row.col.f32.tf32.tf32.f32 "
        "{%0,%1,%2,%3},{%4,%5,%6,%7},{%8,%9},{%0,%1,%2,%3};"
        : "+f"(c[0]), "+f"(c[1]), "+f"(c[2]), "+f"(c[3])
        : "r"(a0), "r"(a1), "r"(a2), "r"(a3), "r"(b0), "r"(b1));
}

// ---------------- device scratch ----------------
__device__ float  g_h0[BB*CC*PLANE];
__device__ float  g_h1[BB*CC*PLANE];
__device__ float2 g_G [BB*CC*HP*KY];
__device__ float2 g_F [BB*CC*MM*KY];
__device__ float2 g_O [BB*CC*MM*KY];
__device__ float2 g_T [BB*CC*HP*KY];
__device__ float  g_Wtr[NLAY*MM*KY*CC*CC];
__device__ float  g_Wti[NLAY*MM*KY*CC*CC];
__device__ float2 g_Ey [KY*HP];
__device__ float2 g_Ex [MM*HP];
__device__ float2 g_Exi[MM*HP];
__device__ float  g_ICy[KY*HP];
__device__ float  g_ISy[KY*HP];
__device__ float  g_tmp[BB*2*SS*SS];

__device__ __forceinline__ float gelu_exact(float x) {
    return 0.5f * x * (1.0f + erff(x * 0.70710678118654752440f));
}

// ---------------- basis tables ----------------
__global__ void k_basis() {
    int idx = blockIdx.x * blockDim.x + threadIdx.x;
    if (idx < KY*HP) {
        int ky = idx / HP, y = idx % HP;
        int r = (ky * y) % HP;
        float a = 6.28318530717958647692f * (float)r / (float)HP;
        float c = cosf(a), s = sinf(a);
        g_Ey[idx] = make_float2(c, -s);
        float al = (ky == 0) ? 1.0f : 2.0f;
        float inv = 1.0f / ((float)HP * (float)HP);
        g_ICy[idx] = al * inv * c;
        g_ISy[idx] = al * inv * s;
    }
    if (idx < MM*HP) {
        int m = idx / HP, xx = idx % HP;
        int kx = (m < KY) ? m : (264 + m);
        int r = (kx * xx) % HP;
        float a = 6.28318530717958647692f * (float)r / (float)HP;
        float c = cosf(a), s = sinf(a);
        g_Ex[idx]  = make_float2(c, -s);
        g_Exi[idx] = make_float2(c,  s);
    }
}

// ---------------- weight transpose ----------------
__global__ void k_transw(const float* __restrict__ w1r, const float* __restrict__ w1i,
                         const float* __restrict__ w2r, const float* __restrict__ w2i) {
    int idx = blockIdx.x * blockDim.x + threadIdx.x;
    if (idx >= NLAY*MM*KY*CC*CC) return;
    int o  = idx & 31;
    int i  = (idx >> 5) & 31;
    int ky = (idx >> 10) % KY;
    int rest = idx / (1024 * KY);
    int m = rest % MM;
    int l = rest / MM;
    const float *sr, *si;
    int src;
    if (m < KY) {
        src = (((l*CC + i)*CC + o)*12 + m)*12 + ky;
        sr = w1r; si = w1i;
    } else {
        src = (((l*CC + i)*CC + o)*12 + (m - 12))*12 + ky;
        sr = w2r; si = w2i;
    }
    g_Wtr[idx] = sr[src];
    g_Wti[idx] = si[src];
}

// ---------------- stage 0: embed ----------------
__global__ void k_embed(const float* __restrict__ xin, const int* __restrict__ d2v,
                        const float* __restrict__ fw, const float* __restrict__ fb,
                        float* __restrict__ hout) {
    int idx = blockIdx.x * blockDim.x + threadIdx.x;
    if (idx >= BB*PLANE) return;
    int b = idx / PLANE;
    int rem = idx % PLANE;
    int i = rem / HP, j = rem % HP;
    float* hp = hout + (size_t)b * CC * PLANE + rem;
    if (i < SS && j < SS) {
        float v  = xin[b*SS*SS + d2v[i*SS + j]];
        float gi = (float)i * (1.0f/255.0f);
        float gj = (float)j * (1.0f/255.0f);
        #pragma unroll
        for (int c = 0; c < CC; c++)
            hp[(size_t)c*PLANE] = fw[c*3]*v + fw[c*3+1]*gi + fw[c*3+2]*gj + fb[c];
    } else {
        #pragma unroll
        for (int c = 0; c < CC; c++) hp[(size_t)c*PLANE] = 0.0f;
    }
}

// ---------------- A: truncated y-DFT as tf32 MMA GEMM ----------------
// Per (b,c): G[288 x 24] = h[288 x 288] * E[288 x 24]  (N = 12 complex modes
// interleaved {re,im} — matches g_G float2 row layout exactly).
// grid (B*C, 3), block 192 = 6 warps x 16 rows = 96 x-rows per block.
__global__ void __launch_bounds__(192) k_ydft(const float* __restrict__ h) {
    __shared__ float sE[HP*24];
    int t = threadIdx.x;
    for (int idx = t; idx < HP*KY; idx += 192) {
        int y = idx % HP, ky = idx / HP;
        float2 e = g_Ey[ky*HP + y];
        sE[y*24 + 2*ky]     = e.x;
        sE[y*24 + 2*ky + 1] = e.y;
    }
    __syncthreads();
    int bc = blockIdx.x;
    int wid = t >> 5, lane = t & 31;
    int lr = lane >> 2, lc = lane & 3;
    int x0 = blockIdx.y * 96 + wid * 16;
    const float* A = h + (size_t)bc * PLANE + (size_t)x0 * HP;

    float acc[3][4];
    #pragma unroll
    for (int nt = 0; nt < 3; nt++)
        #pragma unroll
        for (int j = 0; j < 4; j++) acc[nt][j] = 0.0f;

    #pragma unroll 2
    for (int kb = 0; kb < 36; kb++) {
        int kk = kb*8 + lc;
        float a0f = A[lr*HP + kk];
        float a1f = A[(lr+8)*HP + kk];
        float a2f = A[lr*HP + kk + 4];
        float a3f = A[(lr+8)*HP + kk + 4];
        unsigned ah0, al0, ah1, al1, ah2, al2, ah3, al3;
        tfsplit(a0f, ah0, al0); tfsplit(a1f, ah1, al1);
        tfsplit(a2f, ah2, al2); tfsplit(a3f, ah3, al3);
        #pragma unroll
        for (int nt = 0; nt < 3; nt++) {
            float b0f = sE[kk*24 + nt*8 + lr];
            float b1f = sE[(kk+4)*24 + nt*8 + lr];
            unsigned bh0, bl0, bh1, bl1;
            tfsplit(b0f, bh0, bl0);
            tfsplit(b1f, bh1, bl1);
            mma_tf32(acc[nt], ah0, ah1, ah2, ah3, bl0, bl1);
            mma_tf32(acc[nt], al0, al1, al2, al3, bh0, bh1);
            mma_tf32(acc[nt], ah0, ah1, ah2, ah3, bh0, bh1);
        }
    }

    float2* out0 = g_G + ((size_t)bc * HP + x0 + lr) * KY;
    float2* out1 = out0 + 8 * KY;
    #pragma unroll
    for (int nt = 0; nt < 3; nt++) {
        out0[nt*4 + lc] = make_float2(acc[nt][0], acc[nt][1]);
        out1[nt*4 + lc] = make_float2(acc[nt][2], acc[nt][3]);
    }
}

// ---------------- B: x-DFT onto 24 modes ----------------
__global__ void __launch_bounds__(288) k_xdft() {
    __shared__ float2 sG[HP*KY];
    int bc = blockIdx.x, t = threadIdx.x;
    const float2* Gp = g_G + (size_t)bc * HP * KY;
    for (int i = t; i < HP*KY; i += 288) sG[i] = Gp[i];
    __syncthreads();
    int m = t / KY, ky = t % KY;
    float accx = 0.0f, accy = 0.0f;
    const float2* ex = g_Ex + m * HP;
    for (int x = 0; x < HP; x++) {
        float2 g = sG[x*KY + ky];
        float2 e = ex[x];
        accx += g.x*e.x - g.y*e.y;
        accy += g.x*e.y + g.y*e.x;
    }
    g_F[((size_t)bc * MM + m) * KY + ky] = make_float2(accx, accy);
}

// ---------------- C: complex channel mix ----------------
__global__ void k_mix(int l) {
    int blk = blockIdx.x;
    int b  = blk / (MM*KY);
    int mk = blk % (MM*KY);
    int o = threadIdx.x;
    __shared__ float2 sF[CC];
    sF[o] = g_F[(size_t)(b*CC + o) * (MM*KY) + mk];
    __syncthreads();
    const float* wr = g_Wtr + ((size_t)l * MM * KY + mk) * CC * CC;
    const float* wi = g_Wti + ((size_t)l * MM * KY + mk) * CC * CC;
    float accr = 0.0f, acci = 0.0f;
    #pragma unroll 4
    for (int i = 0; i < CC; i++) {
        float2 f = sF[i];
        float a = wr[i*CC + o], bw = wi[i*CC + o];
        accr += f.x*a  - f.y*bw;
        acci += f.x*bw + f.y*a;
    }
    g_O[(size_t)(b*CC + o) * (MM*KY) + mk] = make_float2(accr, acci);
}

// ---------------- D: inverse x-DFT ----------------
__global__ void __launch_bounds__(288) k_ixdft() {
    __shared__ float2 sO[MM*KY];
    int bc = blockIdx.x, t = threadIdx.x;
    if (t < MM*KY) sO[t] = g_O[(size_t)bc * MM * KY + t];
    __syncthreads();
    float2 acc[KY];
    #pragma unroll
    for (int q = 0; q < KY; q++) acc[q] = make_float2(0.0f, 0.0f);
    #pragma unroll 4
    for (int m = 0; m < MM; m++) {
        float2 e = g_Exi[m*HP + t];
        #pragma unroll
        for (int q = 0; q < KY; q++) {
            float2 o = sO[m*KY + q];
            acc[q].x += o.x*e.x - o.y*e.y;
            acc[q].y += o.x*e.y + o.y*e.x;
        }
    }
    float2* out = g_T + ((size_t)bc * HP + t) * KY;
    #pragma unroll
    for (int q = 0; q < KY; q++) out[q] = acc[q];
}

// ---------------- E: fused conv + inverse y-DFT as one tf32 MMA GEMM ----------------
#define HS 152
#define WS 68
__global__ void __launch_bounds__(128) k_layer(const float* __restrict__ hin,
                                               float* __restrict__ hout,
                                               const float* __restrict__ conv_w,
                                               const float* __restrict__ conv_b,
                                               int l, int dogelu) {
    __shared__ __align__(16) float sH[56*HS];
    __shared__ float sW[32*WS];
    __shared__ float scb[CC];
    int blk = blockIdx.x;
    int b = blk / HP, x = blk % HP;
    int y0 = blockIdx.y * 144;
    int t = threadIdx.x;

    for (int idx = t; idx < 56*36; idx += 128) {
        int r = idx / 36, c4 = (idx % 36) * 4;
        float4 v;
        if (r < 32)
            v = *(const float4*)(hin + (size_t)(b*CC + r)*PLANE + (size_t)x*HP + y0 + c4);
        else if (r < 44)
            v = *(const float4*)(g_ICy + (r-32)*HP + y0 + c4);
        else
            v = *(const float4*)(g_ISy + (r-44)*HP + y0 + c4);
        *(float4*)(sH + r*HS + c4) = v;
    }
    for (int idx = t; idx < 32*56; idx += 128) {
        int o = idx / 56, c = idx % 56;
        float w;
        if (c < 32)
            w = conv_w[l*CC*CC + o*CC + c];
        else if (c < 44)
            w = g_T[((size_t)(b*CC + o)*HP + x)*KY + (c-32)].x;
        else
            w = -g_T[((size_t)(b*CC + o)*HP + x)*KY + (c-44)].y;
        sW[o*WS + c] = w;
    }
    if (t < CC) scb[t] = conv_b[l*CC + t];
    __syncthreads();

    int wid = t >> 5, lane = t & 31;
    int warp_m = wid & 1, warp_n = wid >> 1;
    int lr = lane >> 2, lc = lane & 3;

    float acc[9][4];
    #pragma unroll
    for (int nt = 0; nt < 9; nt++)
        #pragma unroll
        for (int j = 0; j < 4; j++) acc[nt][j] = 0.0f;

    int row0 = warp_m*16 + lr;
    #pragma unroll
    for (int kb = 0; kb < 7; kb++) {
        int kk = kb*8 + lc;
        float a0f = sW[row0*WS + kk];
        float a1f = sW[(row0+8)*WS + kk];
        float a2f = sW[row0*WS + kk + 4];
        float a3f = sW[(row0+8)*WS + kk + 4];
        unsigned ah0, al0, ah1, al1, ah2, al2, ah3, al3;
        tfsplit(a0f, ah0, al0); tfsplit(a1f, ah1, al1);
        tfsplit(a2f, ah2, al2); tfsplit(a3f, ah3, al3);
        #pragma unroll
        for (int nt = 0; nt < 9; nt++) {
            int nb = warp_n*72 + nt*8 + lr;
            float b0f = sH[kk*HS + nb];
            float b1f = sH[(kk+4)*HS + nb];
            unsigned bh0, bl0, bh1, bl1;
            tfsplit(b0f, bh0, bl0);
            tfsplit(b1f, bh1, bl1);
            mma_tf32(acc[nt], ah0, ah1, ah2, ah3, bl0, bl1);
            mma_tf32(acc[nt], al0, al1, al2, al3, bh0, bh1);
            mma_tf32(acc[nt], ah0, ah1, ah2, ah3, bh0, bh1);
        }
    }

    int o0 = warp_m*16 + lr;
    float bia0 = scb[o0], bia1 = scb[o0 + 8];
    float* base0 = hout + (size_t)(b*CC + o0)*PLANE + (size_t)x*HP;
    float* base1 = hout + (size_t)(b*CC + o0 + 8)*PLANE + (size_t)x*HP;
    #pragma unroll
    for (int nt = 0; nt < 9; nt++) {
        int y = y0 + warp_n*72 + nt*8 + 2*lc;
        float v0 = acc[nt][0] + bia0, v1 = acc[nt][1] + bia0;
        float v2 = acc[nt][2] + bia1, v3 = acc[nt][3] + bia1;
        if (dogelu) {
            v0 = gelu_exact(v0); v1 = gelu_exact(v1);
            v2 = gelu_exact(v2); v3 = gelu_exact(v3);
        }
        *(float2*)(base0 + y) = make_float2(v0, v1);
        *(float2*)(base1 + y) = make_float2(v2, v3);
    }
}

// ---------------- final MLP 32 -> 128 (gelu) -> 2, f32x2 ----------------
__global__ void __launch_bounds__(256) k_mlp(const float* __restrict__ hin,
                                             const float* __restrict__ w1,
                                             const float* __restrict__ b1,
                                             const float* __restrict__ w2,
                                             const float* __restrict__ b2) {
    __shared__ __align__(16) ull sw[64*CC];
    __shared__ ull sb[64];
    __shared__ float so0[128], so1[128];
    int t = threadIdx.x;
    for (int idx = t; idx < 64*CC; idx += 256) {
        int k2 = idx >> 5, i = idx & 31;
        sw[idx] = pk(w1[(2*k2)*CC + i], w1[(2*k2+1)*CC + i]);
    }
    if (t < 64) sb[t] = pk(b1[2*t], b1[2*t+1]);
    if (t < 128) { so0[t] = w2[t]; so1[t] = w2[128 + t]; }
    __syncthreads();
    int blk = blockIdx.x;
    int b = blk >> 8, ii = blk & 255;
    const float* hb = hin + (size_t)b * CC * PLANE + (size_t)ii * HP + t;
    ull u2[CC];
    #pragma unroll
    for (int c = 0; c < CC; c++) u2[c] = dup2(hb[(size_t)c * PLANE]);
    float d0 = 0.0f, d1 = 0.0f;
    #pragma unroll 1
    for (int k2 = 0; k2 < 64; k2++) {
        const ulonglong2* wp = (const ulonglong2*)(sw + k2*CC);
        ull za = sb[k2], zb = 0ull, zc = 0ull, zd = 0ull;
        #pragma unroll
        for (int j = 0; j < CC/2; j++) {
            ulonglong2 w = wp[j];
            if (j & 1) { zc = f2fma(w.x, u2[2*j], zc); zd = f2fma(w.y, u2[2*j+1], zd); }
            else       { za = f2fma(w.x, u2[2*j], za); zb = f2fma(w.y, u2[2*j+1], zb); }
        }
        ull z2 = f2add(f2add(za, zb), f2add(zc, zd));
        float z0, z1;
        upk(z0, z1, z2);
        z0 = gelu_exact(z0);
        z1 = gelu_exact(z1);
        d0 += so0[2*k2]*z0 + so0[2*k2+1]*z1;
        d1 += so1[2*k2]*z0 + so1[2*k2+1]*z1;
    }
    int p = ii*SS + t;
    g_tmp[(size_t)(b*2    ) * SS*SS + p] = d0 + __ldg(&b2[0]);
    g_tmp[(size_t)(b*2 + 1) * SS*SS + p] = d1 + __ldg(&b2[1]);
}

// ---------------- output permutation ----------------
__global__ void k_scatter(const int* __restrict__ v2d, float* __restrict__ out) {
    int idx = blockIdx.x * blockDim.x + threadIdx.x;
    if (idx >= BB*SS*SS) return;
    int b = idx >> 16, n = idx & 65535;
    int p = v2d[n];
    float v0 = g_tmp[(size_t)(b*2    ) * SS*SS + p];
    float v1 = g_tmp[(size_t)(b*2 + 1) * SS*SS + p];
    reinterpret_cast<float2*>(out)[idx] = make_float2(v0, v1);
}

// ---------------- launch ----------------
extern "C" void kernel_launch(void* const* d_in, const int* in_sizes, int n_in,
                              void* d_out, int out_size) {
    const float* x    = (const float*)d_in[0];
    const int*   d2v  = (const int*)  d_in[1];
    const int*   v2d  = (const int*)  d_in[2];
    const float* fc0w = (const float*)d_in[3];
    const float* fc0b = (const float*)d_in[4];
    const float* w1r  = (const float*)d_in[5];
    const float* w1i  = (const float*)d_in[6];
    const float* w2r  = (const float*)d_in[7];
    const float* w2i  = (const float*)d_in[8];
    const float* cw   = (const float*)d_in[9];
    const float* cb   = (const float*)d_in[10];
    const float* mw1  = (const float*)d_in[11];
    const float* mb1  = (const float*)d_in[12];
    const float* mw2  = (const float*)d_in[13];
    const float* mb2  = (const float*)d_in[14];

    float *h0, *h1;
    cudaGetSymbolAddress((void**)&h0, g_h0);
    cudaGetSymbolAddress((void**)&h1, g_h1);

    k_basis<<<(MM*HP + 255)/256, 256>>>();
    k_transw<<<(NLAY*MM*KY*CC*CC + 255)/256, 256>>>(w1r, w1i, w2r, w2i);
    k_embed<<<(BB*PLANE + 255)/256, 256>>>(x, d2v, fc0w, fc0b, h0);

    float* cur = h0;
    float* nxt = h1;
    for (int l = 0; l < NLAY; l++) {
        k_ydft<<<dim3(BB*CC, 3), 192>>>(cur);
        k_xdft<<<BB*CC, 288>>>();
        k_mix<<<BB*MM*KY, 32>>>(l);
        k_ixdft<<<BB*CC, 288>>>();
        k_layer<<<dim3(BB*HP, 2), 128>>>(cur, nxt, cw, cb, l, (l < NLAY-1) ? 1 : 0);
        float* tp = cur; cur = nxt; nxt = tp;
    }
    k_mlp<<<BB*SS, 256>>>(cur, mw1, mb1, mw2, mb2);
    k_scatter<<<(BB*SS*SS + 255)/256, 256>>>(v2d, (float*)d_out);
}